// round 2
// baseline (speedup 1.0000x reference)
#include <cuda_runtime.h>
#include <math.h>

// Hopfield layer: 2 iterative attention steps, K=V=Y fixed.
//   step1: tmp = softmax(scale * R·Yᵀ) · Y      (per head)
//   step2: out = softmax(scale * tmp·Yᵀ) · Y
// B=2, L=S=2048, D_MODEL=512, H=8, E=64, scale = 1/8.

#define BM 64      // query rows per block (== threads per block)
#define BN 64      // key tile rows
#define EDIM 64    // head dim
#define EV (EDIM/4)
#define CHUNK 8    // scores kept in registers per online-softmax group

// static scratch for the intermediate q after step 1 (B*L*D = 2*2048*512 floats)
__device__ float g_tmp[2u * 2048u * 512u];

__global__ __launch_bounds__(BM)
void hopfield_attn(const float* __restrict__ Q,   // [B, L, H*E]
                   const float* __restrict__ KV,  // [B, S, H*E]
                   float* __restrict__ O,         // [B, L, H*E]
                   int L, int S)
{
    const int H  = 8;
    const int DM = H * EDIM;  // 512

    const int t   = threadIdx.x;
    const int h   = blockIdx.y;
    const int b   = blockIdx.z;
    const int row = blockIdx.x * BM + t;

    __shared__ float4 kt[BN * EV];   // 64 x 64 floats = 16 KB

    // fold scale into log2e so we can use exp2f
    const float c = 0.125f * 1.4426950408889634f;

    // load this thread's query row into registers (16 x float4)
    float4 q[EV];
    const float4* qrow =
        (const float4*)(Q + ((size_t)b * L + row) * DM + h * EDIM);
#pragma unroll
    for (int i = 0; i < EV; i++) q[i] = qrow[i];

    float4 acc[EV];
#pragma unroll
    for (int i = 0; i < EV; i++) acc[i] = make_float4(0.f, 0.f, 0.f, 0.f);
    float m = -3.0e38f;
    float l = 0.f;

    const float* kvbase = KV + (size_t)b * S * DM + h * EDIM;

    for (int s0 = 0; s0 < S; s0 += BN) {
        __syncthreads();
        // cooperative load of K tile [BN rows x EDIM] as float4s
#pragma unroll
        for (int j = 0; j < (BN * EV) / BM; j++) {
            int f  = j * BM + t;
            int r  = f / EV;
            int c4 = f % EV;
            kt[f] = ((const float4*)(kvbase + (size_t)(s0 + r) * DM))[c4];
        }
        __syncthreads();

#pragma unroll
        for (int g = 0; g < BN; g += CHUNK) {
            // ---- pass 1: scores for CHUNK keys ----
            float sc[CHUNK];
#pragma unroll
            for (int j = 0; j < CHUNK; j++) sc[j] = 0.f;
#pragma unroll
            for (int i = 0; i < EV; i++) {
                float4 qi = q[i];
#pragma unroll
                for (int j = 0; j < CHUNK; j++) {
                    float4 k4 = kt[(g + j) * EV + i];   // warp-broadcast
                    sc[j] += qi.x * k4.x + qi.y * k4.y
                           + qi.z * k4.z + qi.w * k4.w;
                }
            }
            // ---- online softmax update (once per chunk) ----
            float mc = sc[0];
#pragma unroll
            for (int j = 1; j < CHUNK; j++) mc = fmaxf(mc, sc[j]);
            float m_new = fmaxf(m, mc);
            float corr  = exp2f((m - m_new) * c);
            l *= corr;
#pragma unroll
            for (int i = 0; i < EV; i++) {
                acc[i].x *= corr; acc[i].y *= corr;
                acc[i].z *= corr; acc[i].w *= corr;
            }
            m = m_new;
            float p[CHUNK];
#pragma unroll
            for (int j = 0; j < CHUNK; j++) {
                p[j] = exp2f((sc[j] - m) * c);
                l += p[j];
            }
            // ---- pass 2: accumulate p_j * v_j (v == k) ----
#pragma unroll
            for (int i = 0; i < EV; i++) {
                float4 a = acc[i];
#pragma unroll
                for (int j = 0; j < CHUNK; j++) {
                    float4 k4 = kt[(g + j) * EV + i];
                    a.x += p[j] * k4.x; a.y += p[j] * k4.y;
                    a.z += p[j] * k4.z; a.w += p[j] * k4.w;
                }
                acc[i] = a;
            }
        }
    }

    float inv = 1.f / l;
    float4* orow = (float4*)(O + ((size_t)b * L + row) * DM + h * EDIM);
#pragma unroll
    for (int i = 0; i < EV; i++) {
        orow[i] = make_float4(acc[i].x * inv, acc[i].y * inv,
                              acc[i].z * inv, acc[i].w * inv);
    }
}

extern "C" void kernel_launch(void* const* d_in, const int* in_sizes, int n_in,
                              void* d_out, int out_size)
{
    const float* R = (const float*)d_in[0];
    const float* Y = (const float*)d_in[1];
    float* out = (float*)d_out;

    const int B  = 2;
    const int DM = 512;
    const int H  = 8;
    const int L  = in_sizes[0] / (B * DM);   // 2048
    const int S  = in_sizes[1] / (B * DM);   // 2048

    float* tmp = nullptr;
    cudaGetSymbolAddress((void**)&tmp, g_tmp);

    dim3 grid(L / BM, H, B);
    dim3 block(BM);

    // step 1: q = attn(R, Y, Y)
    hopfield_attn<<<grid, block>>>(R, Y, tmp, L, S);
    // step 2: out = attn(q, Y, Y)
    hopfield_attn<<<grid, block>>>(tmp, Y, out, L, S);
}

// round 4
// speedup vs baseline: 32.2176x; 32.2176x over previous
#include <cuda_runtime.h>
#include <cuda_bf16.h>
#include <stdint.h>

// Hopfield layer via warp-level bf16 mma.sync (sm_100 baseline, no tcgen05).
// 2 attention steps, K=V=Y. Per CTA: 64 query rows of one (b,h), 4 warps x 16 rows.
// 3-term bf16 hi/lo error-corrected GEMMs, fp32 accum, unnormalized softmax
// (scores bounded), single normalize at the end.

#define THREADS 128
#define QT 64      // query rows per CTA
#define ST 64      // kv rows per tile
#define DM 512

__device__ float g_tmp[2u * 2048u * 512u];

static __device__ __forceinline__ uint32_t s2u(const void* p) {
    uint32_t a;
    asm("{ .reg .u64 t; cvta.to.shared.u64 t, %1; cvt.u32.u64 %0, t; }"
        : "=r"(a) : "l"(p));
    return a;
}
// swizzled byte offset of (row, 16B-chunk) in a 64x64 bf16 tile (128B rows)
static __device__ __forceinline__ uint32_t off(int row, int chunk) {
    return (uint32_t)(row * 128 + ((chunk ^ (row & 7)) << 4));
}
static __device__ __forceinline__ float ex2f_(float x) {
    float r; asm("ex2.approx.ftz.f32 %0, %1;" : "=f"(r) : "f"(x)); return r;
}
// split two fp32 into packed bf16x2 hi + bf16x2 lo (x -> low half)
static __device__ __forceinline__ void splitpack(float x, float y,
                                                 uint32_t& hi, uint32_t& lo) {
    __nv_bfloat16 hx = __float2bfloat16_rn(x), hy = __float2bfloat16_rn(y);
    float rx = x - __bfloat162float(hx), ry = y - __bfloat162float(hy);
    __nv_bfloat16 lx = __float2bfloat16_rn(rx), ly = __float2bfloat16_rn(ry);
    hi = ((uint32_t)__bfloat16_as_ushort(hy) << 16) | (uint32_t)__bfloat16_as_ushort(hx);
    lo = ((uint32_t)__bfloat16_as_ushort(ly) << 16) | (uint32_t)__bfloat16_as_ushort(lx);
}

static __device__ __forceinline__ void mma_bf16(float c[4], const uint32_t a[4],
                                                const uint32_t b[2]) {
    asm volatile(
        "mma.sync.aligned.m16n8k16.row.col.f32.bf16.bf16.f32 "
        "{%0,%1,%2,%3}, {%4,%5,%6,%7}, {%8,%9}, {%0,%1,%2,%3};"
        : "+f"(c[0]), "+f"(c[1]), "+f"(c[2]), "+f"(c[3])
        : "r"(a[0]), "r"(a[1]), "r"(a[2]), "r"(a[3]), "r"(b[0]), "r"(b[1]));
}
#define LDSM4(r, a) \
    asm volatile("ldmatrix.sync.aligned.m8n8.x4.shared.b16 {%0,%1,%2,%3}, [%4];" \
        : "=r"((r)[0]), "=r"((r)[1]), "=r"((r)[2]), "=r"((r)[3]) : "r"(a))
#define LDSM4T(r, a) \
    asm volatile("ldmatrix.sync.aligned.m8n8.x4.trans.shared.b16 {%0,%1,%2,%3}, [%4];" \
        : "=r"((r)[0]), "=r"((r)[1]), "=r"((r)[2]), "=r"((r)[3]) : "r"(a))

// stage a 64x64 fp32 tile (row stride DM) into swizzled bf16 hi/lo smem tiles
static __device__ __forceinline__ void load_tile(const float* __restrict__ g,
                                                 uint32_t hb, uint32_t lb, int tid) {
#pragma unroll
    for (int i = 0; i < 4; i++) {
        int f = i * 128 + tid;
        int row = f >> 3, c = f & 7;
        const float4* p = (const float4*)(g + (size_t)row * DM + c * 8);
        float4 x0 = p[0], x1 = p[1];
        uint32_t h[4], l[4];
        splitpack(x0.x, x0.y, h[0], l[0]);
        splitpack(x0.z, x0.w, h[1], l[1]);
        splitpack(x1.x, x1.y, h[2], l[2]);
        splitpack(x1.z, x1.w, h[3], l[3]);
        uint32_t o = off(row, c);
        asm volatile("st.shared.v4.b32 [%0], {%1,%2,%3,%4};"
                     :: "r"(hb + o), "r"(h[0]), "r"(h[1]), "r"(h[2]), "r"(h[3]) : "memory");
        asm volatile("st.shared.v4.b32 [%0], {%1,%2,%3,%4};"
                     :: "r"(lb + o), "r"(l[0]), "r"(l[1]), "r"(l[2]), "r"(l[3]) : "memory");
    }
}

__global__ __launch_bounds__(THREADS)
void hopfield_mma(const float* __restrict__ Qm, const float* __restrict__ KVm,
                  float* __restrict__ Om, int L, int S)
{
    __shared__ __align__(16) uint8_t sKH[ST * 128];
    __shared__ __align__(16) uint8_t sKL[ST * 128];
    const uint32_t khb = s2u(sKH), klb = s2u(sKL);

    const int tid = threadIdx.x;
    const int wid = tid >> 5;
    const int lane = tid & 31;
    const int h = blockIdx.y, b = blockIdx.z;
    const float C = 0.125f * 1.4426950408889634f;   // scale * log2(e)

    // ---- prologue: stage Q tile, pull per-warp A fragments (hi/lo) ----
    const float* qg = Qm + ((size_t)b * L + (size_t)blockIdx.x * QT) * DM + h * 64;
    load_tile(qg, khb, klb, tid);
    __syncthreads();

    uint32_t qh[4][4], ql[4][4];
    {
        int row = 16 * wid + (lane & 15);
#pragma unroll
        for (int t = 0; t < 4; t++) {
            int ch = 2 * t + (lane >> 4);
            LDSM4(qh[t], khb + off(row, ch));
            LDSM4(ql[t], klb + off(row, ch));
        }
    }
    __syncthreads();

    float oacc[8][4];
#pragma unroll
    for (int j = 0; j < 8; j++)
#pragma unroll
        for (int i = 0; i < 4; i++) oacc[j][i] = 0.f;
    float l0 = 0.f, l1 = 0.f;

    const float* kg = KVm + (size_t)b * S * DM + h * 64;

    for (int s0 = 0; s0 < S; s0 += ST) {
        load_tile(kg + (size_t)s0 * DM, khb, klb, tid);
        __syncthreads();

        // ---- GEMM1: S[16 x 64] = Q x K^T (3 split terms) ----
        float sc[8][4];
#pragma unroll
        for (int j = 0; j < 8; j++)
#pragma unroll
            for (int i = 0; i < 4; i++) sc[j][i] = 0.f;

#pragma unroll
        for (int j = 0; j < 8; j++) {
            int row = 8 * j + (lane & 7);
            uint32_t bh[8], bl[8];
            LDSM4(bh + 0, khb + off(row, (lane >> 3)));
            LDSM4(bh + 4, khb + off(row, 4 + (lane >> 3)));
            LDSM4(bl + 0, klb + off(row, (lane >> 3)));
            LDSM4(bl + 4, klb + off(row, 4 + (lane >> 3)));
#pragma unroll
            for (int t = 0; t < 4; t++) {
                mma_bf16(sc[j], qh[t], bh + 2 * t);
                mma_bf16(sc[j], qh[t], bl + 2 * t);
                mma_bf16(sc[j], ql[t], bh + 2 * t);
            }
        }

        // ---- softmax (unnormalized): p = exp2(s*C); pack to A-fragments ----
        uint32_t ph[4][4], pl[4][4];
#pragma unroll
        for (int t = 0; t < 4; t++) {
            float e0 = ex2f_(sc[2 * t][0] * C),     e1 = ex2f_(sc[2 * t][1] * C);
            float e2 = ex2f_(sc[2 * t][2] * C),     e3 = ex2f_(sc[2 * t][3] * C);
            float e4 = ex2f_(sc[2 * t + 1][0] * C), e5 = ex2f_(sc[2 * t + 1][1] * C);
            float e6 = ex2f_(sc[2 * t + 1][2] * C), e7 = ex2f_(sc[2 * t + 1][3] * C);
            l0 += (e0 + e1) + (e4 + e5);
            l1 += (e2 + e3) + (e6 + e7);
            splitpack(e0, e1, ph[t][0], pl[t][0]);
            splitpack(e2, e3, ph[t][1], pl[t][1]);
            splitpack(e4, e5, ph[t][2], pl[t][2]);
            splitpack(e6, e7, ph[t][3], pl[t][3]);
        }

        // ---- GEMM2: O += P x V (V == K tile, .trans loads; 3 split terms) ----
#pragma unroll
        for (int t = 0; t < 4; t++) {
            int row = 16 * t + (lane & 7) + (lane & 8);
#pragma unroll
            for (int jp = 0; jp < 4; jp++) {
                int ch = 2 * jp + (lane >> 4);
                uint32_t vh[4], vl[4];
                LDSM4T(vh, khb + off(row, ch));
                LDSM4T(vl, klb + off(row, ch));
                mma_bf16(oacc[2 * jp],     ph[t], vh + 0);
                mma_bf16(oacc[2 * jp],     ph[t], vl + 0);
                mma_bf16(oacc[2 * jp],     pl[t], vh + 0);
                mma_bf16(oacc[2 * jp + 1], ph[t], vh + 2);
                mma_bf16(oacc[2 * jp + 1], ph[t], vl + 2);
                mma_bf16(oacc[2 * jp + 1], pl[t], vh + 2);
            }
        }
        __syncthreads();
    }

    // ---- reduce l across the quad, normalize, store ----
    l0 += __shfl_xor_sync(0xffffffffu, l0, 1);
    l0 += __shfl_xor_sync(0xffffffffu, l0, 2);
    l1 += __shfl_xor_sync(0xffffffffu, l1, 1);
    l1 += __shfl_xor_sync(0xffffffffu, l1, 2);
    float inv0 = 1.f / l0, inv1 = 1.f / l1;

    const int r = lane >> 2, cb = (lane & 3) * 2;
    float* og = Om + ((size_t)b * L + (size_t)blockIdx.x * QT + 16 * wid) * DM + h * 64;
#pragma unroll
    for (int j = 0; j < 8; j++) {
        *(float2*)(og + (size_t)r * DM + 8 * j + cb) =
            make_float2(oacc[j][0] * inv0, oacc[j][1] * inv0);
        *(float2*)(og + (size_t)(r + 8) * DM + 8 * j + cb) =
            make_float2(oacc[j][2] * inv1, oacc[j][3] * inv1);
    }
}

extern "C" void kernel_launch(void* const* d_in, const int* in_sizes, int n_in,
                              void* d_out, int out_size)
{
    const float* R = (const float*)d_in[0];
    const float* Y = (const float*)d_in[1];
    float* out = (float*)d_out;

    const int B = 2, H = 8;
    const int L = in_sizes[0] / (B * DM);   // 2048
    const int S = in_sizes[1] / (B * DM);   // 2048

    float* tmp = nullptr;
    cudaGetSymbolAddress((void**)&tmp, g_tmp);

    dim3 grid(L / QT, H, B);
    dim3 block(THREADS);
    hopfield_mma<<<grid, block>>>(R, Y, tmp, L, S);
    hopfield_mma<<<grid, block>>>(tmp, Y, out, L, S);
}

// round 5
// speedup vs baseline: 40.1293x; 1.2456x over previous
#include <cuda_runtime.h>
#include <cuda_bf16.h>
#include <stdint.h>

// Hopfield layer via warp-level bf16 mma.sync (sm_100, no tcgen05 on this target).
// R5: pre-split inputs to bf16 hi/lo in gmem; cp.async double-buffered KV tiles;
// 32 query rows per warp (2x A-reuse). 3-term error-corrected bf16 GEMMs,
// fp32 accum, unnormalized softmax (bounded scores), single normalize at end.

#define DM 512
#define QT 128     // query rows per CTA (4 warps x 32 rows)
#define ST 64      // kv rows per tile
#define THREADS 128

// pre-split global buffers (bf16 hi/lo), 6 x 4MB
#define NELEM (2u * 2048u * 512u)
__device__ __nv_bfloat16 gYh[NELEM], gYl[NELEM];
__device__ __nv_bfloat16 gRh[NELEM], gRl[NELEM];
__device__ __nv_bfloat16 gTh[NELEM], gTl[NELEM];

static __device__ __forceinline__ uint32_t s2u(const void* p) {
    uint32_t a;
    asm("{ .reg .u64 t; cvta.to.shared.u64 t, %1; cvt.u32.u64 %0, t; }"
        : "=r"(a) : "l"(p));
    return a;
}
// swizzled byte offset of (row, 16B-chunk) in a 64-row x 128B tile
static __device__ __forceinline__ uint32_t off(int row, int chunk) {
    return (uint32_t)(row * 128 + ((chunk ^ (row & 7)) << 4));
}
static __device__ __forceinline__ float ex2f_(float x) {
    float r; asm("ex2.approx.ftz.f32 %0, %1;" : "=f"(r) : "f"(x)); return r;
}
static __device__ __forceinline__ void splitpack(float x, float y,
                                                 uint32_t& hi, uint32_t& lo) {
    __nv_bfloat16 hx = __float2bfloat16_rn(x), hy = __float2bfloat16_rn(y);
    float rx = x - __bfloat162float(hx), ry = y - __bfloat162float(hy);
    __nv_bfloat16 lx = __float2bfloat16_rn(rx), ly = __float2bfloat16_rn(ry);
    hi = ((uint32_t)__bfloat16_as_ushort(hy) << 16) | (uint32_t)__bfloat16_as_ushort(hx);
    lo = ((uint32_t)__bfloat16_as_ushort(ly) << 16) | (uint32_t)__bfloat16_as_ushort(lx);
}

static __device__ __forceinline__ void mma_bf16(float c[4], const uint32_t a[4],
                                                const uint32_t b[2]) {
    asm volatile(
        "mma.sync.aligned.m16n8k16.row.col.f32.bf16.bf16.f32 "
        "{%0,%1,%2,%3}, {%4,%5,%6,%7}, {%8,%9}, {%0,%1,%2,%3};"
        : "+f"(c[0]), "+f"(c[1]), "+f"(c[2]), "+f"(c[3])
        : "r"(a[0]), "r"(a[1]), "r"(a[2]), "r"(a[3]), "r"(b[0]), "r"(b[1]));
}
#define LDSM4(r, a) \
    asm volatile("ldmatrix.sync.aligned.m8n8.x4.shared.b16 {%0,%1,%2,%3}, [%4];" \
        : "=r"((r)[0]), "=r"((r)[1]), "=r"((r)[2]), "=r"((r)[3]) : "r"(a))
#define LDSM4T(r, a) \
    asm volatile("ldmatrix.sync.aligned.m8n8.x4.trans.shared.b16 {%0,%1,%2,%3}, [%4];" \
        : "=r"((r)[0]), "=r"((r)[1]), "=r"((r)[2]), "=r"((r)[3]) : "r"(a))
#define CPA(dst, src) \
    asm volatile("cp.async.cg.shared.global [%0], [%1], 16;" :: "r"(dst), "l"(src))
#define CPC() asm volatile("cp.async.commit_group;" ::: "memory")
#define CPW(n) asm volatile("cp.async.wait_group %0;" :: "n"(n) : "memory")

// ---- pre-split: fp32 -> bf16 hi + bf16 lo (packed pairs) ----
__global__ void presplit(const float4* __restrict__ src, uint2* __restrict__ hi,
                         uint2* __restrict__ lo, int n4)
{
    int i = blockIdx.x * blockDim.x + threadIdx.x;
    if (i < n4) {
        float4 x = src[i];
        uint32_t h0, l0, h1, l1;
        splitpack(x.x, x.y, h0, l0);
        splitpack(x.z, x.w, h1, l1);
        hi[i] = make_uint2(h0, h1);
        lo[i] = make_uint2(l0, l1);
    }
}

__global__ __launch_bounds__(THREADS, 1)
void hopfield_mma(const __nv_bfloat16* __restrict__ Qh, const __nv_bfloat16* __restrict__ Ql,
                  const __nv_bfloat16* __restrict__ Kh, const __nv_bfloat16* __restrict__ Kl,
                  float* __restrict__ outF,
                  __nv_bfloat16* __restrict__ outH, __nv_bfloat16* __restrict__ outL,
                  int L, int S)
{
    __shared__ __align__(16) uint8_t sH[2][ST * 128];
    __shared__ __align__(16) uint8_t sL[2][ST * 128];
    const uint32_t hb0 = s2u(sH[0]), hb1 = s2u(sH[1]);
    const uint32_t lb0 = s2u(sL[0]), lb1 = s2u(sL[1]);

    const int tid = threadIdx.x;
    const int wid = tid >> 5;
    const int lane = tid & 31;
    const int h = blockIdx.y, b = blockIdx.z;
    const float C = 0.125f * 1.4426950408889634f;

    // ---- stage Q tile (128 rows) through both smem buffers via cp.async ----
    const __nv_bfloat16* qg = Qh + ((size_t)b * L + (size_t)blockIdx.x * QT) * DM + h * 64;
    const __nv_bfloat16* qgl = Ql + ((size_t)b * L + (size_t)blockIdx.x * QT) * DM + h * 64;
    {
        int c = tid & 7, r0 = tid >> 3;   // r0 in 0..15
#pragma unroll
        for (int i = 0; i < 8; i++) {
            int row = r0 + i * 16;        // 0..127
            uint32_t hd = (row < 64 ? hb0 : hb1) + off(row & 63, c);
            uint32_t ld = (row < 64 ? lb0 : lb1) + off(row & 63, c);
            const char* hs = (const char*)(qg + (size_t)row * DM) + c * 16;
            const char* ls = (const char*)(qgl + (size_t)row * DM) + c * 16;
            CPA(hd, hs);
            CPA(ld, ls);
        }
        CPC(); CPW(0);
    }
    __syncthreads();

    // per-warp A fragments: 2 row-tiles of 16 x 64 (hi/lo)
    uint32_t qfh[2][4][4], qfl[2][4][4];
#pragma unroll
    for (int rt = 0; rt < 2; rt++) {
        int gr = 32 * wid + 16 * rt + (lane & 15);   // row within Q tile
        uint32_t hbq = (gr < 64 ? hb0 : hb1);
        uint32_t lbq = (gr < 64 ? lb0 : lb1);
        int lr = gr & 63;
#pragma unroll
        for (int t = 0; t < 4; t++) {
            int ch = 2 * t + (lane >> 4);
            LDSM4(qfh[rt][t], hbq + off(lr, ch));
            LDSM4(qfl[rt][t], lbq + off(lr, ch));
        }
    }
    __syncthreads();

    float oacc[2][8][4];
#pragma unroll
    for (int rt = 0; rt < 2; rt++)
#pragma unroll
        for (int j = 0; j < 8; j++)
#pragma unroll
            for (int i = 0; i < 4; i++) oacc[rt][j][i] = 0.f;
    float lsum[2][2] = {{0.f, 0.f}, {0.f, 0.f}};

    const __nv_bfloat16* kg = Kh + (size_t)b * S * DM + h * 64;
    const __nv_bfloat16* kgl = Kl + (size_t)b * S * DM + h * 64;
    const int NT = S / ST;   // 32

    // prefetch tiles 0, 1
    {
        int c = tid & 7, r0 = tid >> 3;
#pragma unroll
        for (int pf = 0; pf < 2; pf++) {
            uint32_t hbb = pf ? hb1 : hb0, lbb = pf ? lb1 : lb0;
            const char* hs = (const char*)(kg + (size_t)pf * ST * DM);
            const char* ls = (const char*)(kgl + (size_t)pf * ST * DM);
#pragma unroll
            for (int i = 0; i < 4; i++) {
                int row = r0 + i * 16;
                CPA(hbb + off(row, c), hs + (size_t)row * DM * 2 + c * 16);
                CPA(lbb + off(row, c), ls + (size_t)row * DM * 2 + c * 16);
            }
            CPC();
        }
    }

    for (int t = 0; t < NT; t++) {
        CPW(1);
        __syncthreads();
        const uint32_t hbb = (t & 1) ? hb1 : hb0;
        const uint32_t lbb = (t & 1) ? lb1 : lb0;

        // ---- GEMM1: sc[rt][16 x 64] = Q x K^T (3 split terms) ----
        float sc[2][8][4];
#pragma unroll
        for (int rt = 0; rt < 2; rt++)
#pragma unroll
            for (int j = 0; j < 8; j++)
#pragma unroll
                for (int i = 0; i < 4; i++) sc[rt][j][i] = 0.f;

#pragma unroll
        for (int j = 0; j < 8; j++) {
            int row = 8 * j + (lane & 7);
            uint32_t bh[8], bl[8];
            LDSM4(bh + 0, hbb + off(row, (lane >> 3)));
            LDSM4(bh + 4, hbb + off(row, 4 + (lane >> 3)));
            LDSM4(bl + 0, lbb + off(row, (lane >> 3)));
            LDSM4(bl + 4, lbb + off(row, 4 + (lane >> 3)));
#pragma unroll
            for (int t4 = 0; t4 < 4; t4++) {
#pragma unroll
                for (int rt = 0; rt < 2; rt++) {
                    mma_bf16(sc[rt][j], qfh[rt][t4], bh + 2 * t4);
                    mma_bf16(sc[rt][j], qfh[rt][t4], bl + 2 * t4);
                    mma_bf16(sc[rt][j], qfl[rt][t4], bh + 2 * t4);
                }
            }
        }

        // ---- softmax (unnormalized), pack P to A-fragments ----
        uint32_t ph[2][4][4], pl[2][4][4];
#pragma unroll
        for (int rt = 0; rt < 2; rt++) {
#pragma unroll
            for (int t4 = 0; t4 < 4; t4++) {
                float e0 = ex2f_(sc[rt][2 * t4][0] * C),     e1 = ex2f_(sc[rt][2 * t4][1] * C);
                float e2 = ex2f_(sc[rt][2 * t4][2] * C),     e3 = ex2f_(sc[rt][2 * t4][3] * C);
                float e4 = ex2f_(sc[rt][2 * t4 + 1][0] * C), e5 = ex2f_(sc[rt][2 * t4 + 1][1] * C);
                float e6 = ex2f_(sc[rt][2 * t4 + 1][2] * C), e7 = ex2f_(sc[rt][2 * t4 + 1][3] * C);
                lsum[rt][0] += (e0 + e1) + (e4 + e5);
                lsum[rt][1] += (e2 + e3) + (e6 + e7);
                splitpack(e0, e1, ph[rt][t4][0], pl[rt][t4][0]);
                splitpack(e2, e3, ph[rt][t4][1], pl[rt][t4][1]);
                splitpack(e4, e5, ph[rt][t4][2], pl[rt][t4][2]);
                splitpack(e6, e7, ph[rt][t4][3], pl[rt][t4][3]);
            }
        }

        // ---- GEMM2: O += P x V (V == K tile, .trans; 3 split terms) ----
#pragma unroll
        for (int t4 = 0; t4 < 4; t4++) {
            int row = 16 * t4 + (lane & 7) + (lane & 8);
#pragma unroll
            for (int jp = 0; jp < 4; jp++) {
                int ch = 2 * jp + (lane >> 4);
                uint32_t vh[4], vl[4];
                LDSM4T(vh, hbb + off(row, ch));
                LDSM4T(vl, lbb + off(row, ch));
#pragma unroll
                for (int rt = 0; rt < 2; rt++) {
                    mma_bf16(oacc[rt][2 * jp],     ph[rt][t4], vh + 0);
                    mma_bf16(oacc[rt][2 * jp],     ph[rt][t4], vl + 0);
                    mma_bf16(oacc[rt][2 * jp],     pl[rt][t4], vh + 0);
                    mma_bf16(oacc[rt][2 * jp + 1], ph[rt][t4], vh + 2);
                    mma_bf16(oacc[rt][2 * jp + 1], ph[rt][t4], vl + 2);
                    mma_bf16(oacc[rt][2 * jp + 1], pl[rt][t4], vh + 2);
                }
            }
        }
        __syncthreads();

        // prefetch tile t+2 into the buffer just freed
        if (t + 2 < NT) {
            int c = tid & 7, r0 = tid >> 3;
            const char* hs = (const char*)(kg + (size_t)(t + 2) * ST * DM);
            const char* ls = (const char*)(kgl + (size_t)(t + 2) * ST * DM);
#pragma unroll
            for (int i = 0; i < 4; i++) {
                int row = r0 + i * 16;
                CPA(hbb + off(row, c), hs + (size_t)row * DM * 2 + c * 16);
                CPA(lbb + off(row, c), ls + (size_t)row * DM * 2 + c * 16);
            }
        }
        CPC();
    }

    // ---- normalize + store ----
    const int r = lane >> 2, cb = (lane & 3) * 2;
#pragma unroll
    for (int rt = 0; rt < 2; rt++) {
        float l0 = lsum[rt][0], l1 = lsum[rt][1];
        l0 += __shfl_xor_sync(0xffffffffu, l0, 1);
        l0 += __shfl_xor_sync(0xffffffffu, l0, 2);
        l1 += __shfl_xor_sync(0xffffffffu, l1, 1);
        l1 += __shfl_xor_sync(0xffffffffu, l1, 2);
        float inv0 = 1.f / l0, inv1 = 1.f / l1;

        size_t base = ((size_t)b * L + (size_t)blockIdx.x * QT + 32 * wid + 16 * rt) * DM
                    + h * 64;
        if (outF) {
#pragma unroll
            for (int j = 0; j < 8; j++) {
                *(float2*)(outF + base + (size_t)r * DM + 8 * j + cb) =
                    make_float2(oacc[rt][j][0] * inv0, oacc[rt][j][1] * inv0);
                *(float2*)(outF + base + (size_t)(r + 8) * DM + 8 * j + cb) =
                    make_float2(oacc[rt][j][2] * inv1, oacc[rt][j][3] * inv1);
            }
        } else {
#pragma unroll
            for (int j = 0; j < 8; j++) {
                uint32_t h0, l0p, h1, l1p;
                splitpack(oacc[rt][j][0] * inv0, oacc[rt][j][1] * inv0, h0, l0p);
                splitpack(oacc[rt][j][2] * inv1, oacc[rt][j][3] * inv1, h1, l1p);
                *(uint32_t*)(outH + base + (size_t)r * DM + 8 * j + cb) = h0;
                *(uint32_t*)(outL + base + (size_t)r * DM + 8 * j + cb) = l0p;
                *(uint32_t*)(outH + base + (size_t)(r + 8) * DM + 8 * j + cb) = h1;
                *(uint32_t*)(outL + base + (size_t)(r + 8) * DM + 8 * j + cb) = l1p;
            }
        }
    }
}

extern "C" void kernel_launch(void* const* d_in, const int* in_sizes, int n_in,
                              void* d_out, int out_size)
{
    const float* R = (const float*)d_in[0];
    const float* Y = (const float*)d_in[1];
    float* out = (float*)d_out;

    const int B = 2, H = 8;
    const int L = in_sizes[0] / (B * DM);   // 2048
    const int S = in_sizes[1] / (B * DM);   // 2048

    __nv_bfloat16 *Yh, *Yl, *Rh, *Rl, *Th, *Tl;
    cudaGetSymbolAddress((void**)&Yh, gYh);
    cudaGetSymbolAddress((void**)&Yl, gYl);
    cudaGetSymbolAddress((void**)&Rh, gRh);
    cudaGetSymbolAddress((void**)&Rl, gRl);
    cudaGetSymbolAddress((void**)&Th, gTh);
    cudaGetSymbolAddress((void**)&Tl, gTl);

    const int n4 = (int)(NELEM / 4);
    presplit<<<(n4 + 255) / 256, 256>>>((const float4*)Y, (uint2*)Yh, (uint2*)Yl, n4);
    presplit<<<(n4 + 255) / 256, 256>>>((const float4*)R, (uint2*)Rh, (uint2*)Rl, n4);

    dim3 grid(L / QT, H, B);
    dim3 block(THREADS);
    // step 1: Q=R -> split tmp
    hopfield_mma<<<grid, block>>>(Rh, Rl, Yh, Yl, nullptr, Th, Tl, L, S);
    // step 2: Q=tmp -> fp32 out
    hopfield_mma<<<grid, block>>>(Th, Tl, Yh, Yl, out, nullptr, nullptr, L, S);
}

// round 6
// speedup vs baseline: 43.4800x; 1.0835x over previous
#include <cuda_runtime.h>
#include <cuda_bf16.h>
#include <stdint.h>

// Hopfield layer via warp-level bf16 mma.sync (sm_100, tcgen05 not in compile target).
// R6: 256 threads / 8 warps per CTA (2 warps/SMSP), 16 query rows per warp,
// pre-split bf16 hi/lo inputs, cp.async double-buffered KV tiles.
// 3-term error-corrected bf16 GEMMs, fp32 accum, unnormalized softmax
// (bounded scores), single normalize at end.

#define DM 512
#define QT 128     // query rows per CTA (8 warps x 16 rows)
#define ST 64      // kv rows per tile
#define THREADS 256

#define NELEM (2u * 2048u * 512u)
__device__ __nv_bfloat16 gYh[NELEM], gYl[NELEM];
__device__ __nv_bfloat16 gRh[NELEM], gRl[NELEM];
__device__ __nv_bfloat16 gTh[NELEM], gTl[NELEM];

static __device__ __forceinline__ uint32_t s2u(const void* p) {
    uint32_t a;
    asm("{ .reg .u64 t; cvta.to.shared.u64 t, %1; cvt.u32.u64 %0, t; }"
        : "=r"(a) : "l"(p));
    return a;
}
// swizzled byte offset of (row, 16B-chunk) in a 64-row x 128B tile
static __device__ __forceinline__ uint32_t off(int row, int chunk) {
    return (uint32_t)(row * 128 + ((chunk ^ (row & 7)) << 4));
}
static __device__ __forceinline__ float ex2f_(float x) {
    float r; asm("ex2.approx.ftz.f32 %0, %1;" : "=f"(r) : "f"(x)); return r;
}
static __device__ __forceinline__ void splitpack(float x, float y,
                                                 uint32_t& hi, uint32_t& lo) {
    __nv_bfloat16 hx = __float2bfloat16_rn(x), hy = __float2bfloat16_rn(y);
    float rx = x - __bfloat162float(hx), ry = y - __bfloat162float(hy);
    __nv_bfloat16 lx = __float2bfloat16_rn(rx), ly = __float2bfloat16_rn(ry);
    hi = ((uint32_t)__bfloat16_as_ushort(hy) << 16) | (uint32_t)__bfloat16_as_ushort(hx);
    lo = ((uint32_t)__bfloat16_as_ushort(ly) << 16) | (uint32_t)__bfloat16_as_ushort(lx);
}

static __device__ __forceinline__ void mma_bf16(float c[4], const uint32_t a[4],
                                                const uint32_t b[2]) {
    asm volatile(
        "mma.sync.aligned.m16n8k16.row.col.f32.bf16.bf16.f32 "
        "{%0,%1,%2,%3}, {%4,%5,%6,%7}, {%8,%9}, {%0,%1,%2,%3};"
        : "+f"(c[0]), "+f"(c[1]), "+f"(c[2]), "+f"(c[3])
        : "r"(a[0]), "r"(a[1]), "r"(a[2]), "r"(a[3]), "r"(b[0]), "r"(b[1]));
}
#define LDSM4(r, a) \
    asm volatile("ldmatrix.sync.aligned.m8n8.x4.shared.b16 {%0,%1,%2,%3}, [%4];" \
        : "=r"((r)[0]), "=r"((r)[1]), "=r"((r)[2]), "=r"((r)[3]) : "r"(a))
#define LDSM4T(r, a) \
    asm volatile("ldmatrix.sync.aligned.m8n8.x4.trans.shared.b16 {%0,%1,%2,%3}, [%4];" \
        : "=r"((r)[0]), "=r"((r)[1]), "=r"((r)[2]), "=r"((r)[3]) : "r"(a))
#define CPA(dst, src) \
    asm volatile("cp.async.cg.shared.global [%0], [%1], 16;" :: "r"(dst), "l"(src))
#define CPC() asm volatile("cp.async.commit_group;" ::: "memory")
#define CPW(n) asm volatile("cp.async.wait_group %0;" :: "n"(n) : "memory")

// ---- pre-split: fp32 -> bf16 hi + bf16 lo (packed pairs) ----
__global__ void presplit(const float4* __restrict__ src, uint2* __restrict__ hi,
                         uint2* __restrict__ lo, int n4)
{
    int i = blockIdx.x * blockDim.x + threadIdx.x;
    if (i < n4) {
        float4 x = src[i];
        uint32_t h0, l0, h1, l1;
        splitpack(x.x, x.y, h0, l0);
        splitpack(x.z, x.w, h1, l1);
        hi[i] = make_uint2(h0, h1);
        lo[i] = make_uint2(l0, l1);
    }
}

__global__ __launch_bounds__(THREADS, 1)
void hopfield_mma(const __nv_bfloat16* __restrict__ Qh, const __nv_bfloat16* __restrict__ Ql,
                  const __nv_bfloat16* __restrict__ Kh, const __nv_bfloat16* __restrict__ Kl,
                  float* __restrict__ outF,
                  __nv_bfloat16* __restrict__ outH, __nv_bfloat16* __restrict__ outL,
                  int L, int S)
{
    __shared__ __align__(16) uint8_t sH[2][ST * 128];
    __shared__ __align__(16) uint8_t sL[2][ST * 128];
    const uint32_t hb0 = s2u(sH[0]), hb1 = s2u(sH[1]);
    const uint32_t lb0 = s2u(sL[0]), lb1 = s2u(sL[1]);

    const int tid = threadIdx.x;
    const int wid = tid >> 5;
    const int lane = tid & 31;
    const int h = blockIdx.y, b = blockIdx.z;
    const float C = 0.125f * 1.4426950408889634f;

    // ---- stage Q tile (128 rows) through both smem buffers via cp.async ----
    const __nv_bfloat16* qg = Qh + ((size_t)b * L + (size_t)blockIdx.x * QT) * DM + h * 64;
    const __nv_bfloat16* qgl = Ql + ((size_t)b * L + (size_t)blockIdx.x * QT) * DM + h * 64;
    {
        int c = tid & 7, r0 = tid >> 3;   // r0 in 0..31
#pragma unroll
        for (int i = 0; i < 4; i++) {
            int row = r0 + i * 32;        // 0..127
            uint32_t hd = (row < 64 ? hb0 : hb1) + off(row & 63, c);
            uint32_t ld = (row < 64 ? lb0 : lb1) + off(row & 63, c);
            CPA(hd, (const char*)(qg + (size_t)row * DM) + c * 16);
            CPA(ld, (const char*)(qgl + (size_t)row * DM) + c * 16);
        }
        CPC(); CPW(0);
    }
    __syncthreads();

    // per-warp A fragments: 16 x 64 (hi/lo); warp w owns rows 16w..16w+15
    uint32_t qfh[4][4], qfl[4][4];
    {
        int gr = 16 * wid + (lane & 15);
        uint32_t hbq = (gr < 64 ? hb0 : hb1);
        uint32_t lbq = (gr < 64 ? lb0 : lb1);
        int lr = gr & 63;
#pragma unroll
        for (int t = 0; t < 4; t++) {
            int ch = 2 * t + (lane >> 4);
            LDSM4(qfh[t], hbq + off(lr, ch));
            LDSM4(qfl[t], lbq + off(lr, ch));
        }
    }
    __syncthreads();

    float oacc[8][4];
#pragma unroll
    for (int j = 0; j < 8; j++)
#pragma unroll
        for (int i = 0; i < 4; i++) oacc[j][i] = 0.f;
    float l0 = 0.f, l1 = 0.f;

    const __nv_bfloat16* kg = Kh + (size_t)b * S * DM + h * 64;
    const __nv_bfloat16* kgl = Kl + (size_t)b * S * DM + h * 64;
    const int NT = S / ST;   // 32

    // prefetch tiles 0, 1
    {
        int c = tid & 7, r0 = tid >> 3;   // 0..31
#pragma unroll
        for (int pf = 0; pf < 2; pf++) {
            uint32_t hbb = pf ? hb1 : hb0, lbb = pf ? lb1 : lb0;
            const char* hs = (const char*)(kg + (size_t)pf * ST * DM);
            const char* ls = (const char*)(kgl + (size_t)pf * ST * DM);
#pragma unroll
            for (int i = 0; i < 2; i++) {
                int row = r0 + i * 32;
                CPA(hbb + off(row, c), hs + (size_t)row * DM * 2 + c * 16);
                CPA(lbb + off(row, c), ls + (size_t)row * DM * 2 + c * 16);
            }
            CPC();
        }
    }

    for (int t = 0; t < NT; t++) {
        CPW(1);
        __syncthreads();
        const uint32_t hbb = (t & 1) ? hb1 : hb0;
        const uint32_t lbb = (t & 1) ? lb1 : lb0;

        // ---- GEMM1: sc[16 x 64] = Q x K^T (3 split terms) ----
        float sc[8][4];
#pragma unroll
        for (int j = 0; j < 8; j++)
#pragma unroll
            for (int i = 0; i < 4; i++) sc[j][i] = 0.f;

#pragma unroll
        for (int j = 0; j < 8; j++) {
            int row = 8 * j + (lane & 7);
            uint32_t bh[8], bl[8];
            LDSM4(bh + 0, hbb + off(row, (lane >> 3)));
            LDSM4(bh + 4, hbb + off(row, 4 + (lane >> 3)));
            LDSM4(bl + 0, lbb + off(row, (lane >> 3)));
            LDSM4(bl + 4, lbb + off(row, 4 + (lane >> 3)));
#pragma unroll
            for (int t4 = 0; t4 < 4; t4++) {
                mma_bf16(sc[j], qfh[t4], bh + 2 * t4);
                mma_bf16(sc[j], qfh[t4], bl + 2 * t4);
                mma_bf16(sc[j], qfl[t4], bh + 2 * t4);
            }
        }

        // ---- softmax (unnormalized), pack P to A-fragments ----
        uint32_t ph[4][4], pl[4][4];
#pragma unroll
        for (int t4 = 0; t4 < 4; t4++) {
            float e0 = ex2f_(sc[2 * t4][0] * C),     e1 = ex2f_(sc[2 * t4][1] * C);
            float e2 = ex2f_(sc[2 * t4][2] * C),     e3 = ex2f_(sc[2 * t4][3] * C);
            float e4 = ex2f_(sc[2 * t4 + 1][0] * C), e5 = ex2f_(sc[2 * t4 + 1][1] * C);
            float e6 = ex2f_(sc[2 * t4 + 1][2] * C), e7 = ex2f_(sc[2 * t4 + 1][3] * C);
            l0 += (e0 + e1) + (e4 + e5);
            l1 += (e2 + e3) + (e6 + e7);
            splitpack(e0, e1, ph[t4][0], pl[t4][0]);
            splitpack(e2, e3, ph[t4][1], pl[t4][1]);
            splitpack(e4, e5, ph[t4][2], pl[t4][2]);
            splitpack(e6, e7, ph[t4][3], pl[t4][3]);
        }

        // ---- GEMM2: O += P x V (V == K tile, .trans; 3 split terms) ----
#pragma unroll
        for (int t4 = 0; t4 < 4; t4++) {
            int row = 16 * t4 + (lane & 7) + (lane & 8);
#pragma unroll
            for (int jp = 0; jp < 4; jp++) {
                int ch = 2 * jp + (lane >> 4);
                uint32_t vh[4], vl[4];
                LDSM4T(vh, hbb + off(row, ch));
                LDSM4T(vl, lbb + off(row, ch));
                mma_bf16(oacc[2 * jp],     ph[t4], vh + 0);
                mma_bf16(oacc[2 * jp],     ph[t4], vl + 0);
                mma_bf16(oacc[2 * jp],     pl[t4], vh + 0);
                mma_bf16(oacc[2 * jp + 1], ph[t4], vh + 2);
                mma_bf16(oacc[2 * jp + 1], ph[t4], vl + 2);
                mma_bf16(oacc[2 * jp + 1], pl[t4], vh + 2);
            }
        }
        __syncthreads();

        // prefetch tile t+2 into the buffer just freed
        if (t + 2 < NT) {
            int c = tid & 7, r0 = tid >> 3;
            const char* hs = (const char*)(kg + (size_t)(t + 2) * ST * DM);
            const char* ls = (const char*)(kgl + (size_t)(t + 2) * ST * DM);
#pragma unroll
            for (int i = 0; i < 2; i++) {
                int row = r0 + i * 32;
                CPA(hbb + off(row, c), hs + (size_t)row * DM * 2 + c * 16);
                CPA(lbb + off(row, c), ls + (size_t)row * DM * 2 + c * 16);
            }
        }
        CPC();
    }

    // ---- normalize + store ----
    l0 += __shfl_xor_sync(0xffffffffu, l0, 1);
    l0 += __shfl_xor_sync(0xffffffffu, l0, 2);
    l1 += __shfl_xor_sync(0xffffffffu, l1, 1);
    l1 += __shfl_xor_sync(0xffffffffu, l1, 2);
    float inv0 = 1.f / l0, inv1 = 1.f / l1;

    const int r = lane >> 2, cb = (lane & 3) * 2;
    size_t base = ((size_t)b * L + (size_t)blockIdx.x * QT + 16 * wid) * DM + h * 64;
    if (outF) {
#pragma unroll
        for (int j = 0; j < 8; j++) {
            *(float2*)(outF + base + (size_t)r * DM + 8 * j + cb) =
                make_float2(oacc[j][0] * inv0, oacc[j][1] * inv0);
            *(float2*)(outF + base + (size_t)(r + 8) * DM + 8 * j + cb) =
                make_float2(oacc[j][2] * inv1, oacc[j][3] * inv1);
        }
    } else {
#pragma unroll
        for (int j = 0; j < 8; j++) {
            uint32_t h0, lp0, h1, lp1;
            splitpack(oacc[j][0] * inv0, oacc[j][1] * inv0, h0, lp0);
            splitpack(oacc[j][2] * inv1, oacc[j][3] * inv1, h1, lp1);
            *(uint32_t*)(outH + base + (size_t)r * DM + 8 * j + cb) = h0;
            *(uint32_t*)(outL + base + (size_t)r * DM + 8 * j + cb) = lp0;
            *(uint32_t*)(outH + base + (size_t)(r + 8) * DM + 8 * j + cb) = h1;
            *(uint32_t*)(outL + base + (size_t)(r + 8) * DM + 8 * j + cb) = lp1;
        }
    }
}

extern "C" void kernel_launch(void* const* d_in, const int* in_sizes, int n_in,
                              void* d_out, int out_size)
{
    const float* R = (const float*)d_in[0];
    const float* Y = (const float*)d_in[1];
    float* out = (float*)d_out;

    const int B = 2, H = 8;
    const int L = in_sizes[0] / (B * DM);   // 2048
    const int S = in_sizes[1] / (B * DM);   // 2048

    __nv_bfloat16 *Yh, *Yl, *Rh, *Rl, *Th, *Tl;
    cudaGetSymbolAddress((void**)&Yh, gYh);
    cudaGetSymbolAddress((void**)&Yl, gYl);
    cudaGetSymbolAddress((void**)&Rh, gRh);
    cudaGetSymbolAddress((void**)&Rl, gRl);
    cudaGetSymbolAddress((void**)&Th, gTh);
    cudaGetSymbolAddress((void**)&Tl, gTl);

    const int n4 = (int)(NELEM / 4);
    presplit<<<(n4 + 255) / 256, 256>>>((const float4*)Y, (uint2*)Yh, (uint2*)Yl, n4);
    presplit<<<(n4 + 255) / 256, 256>>>((const float4*)R, (uint2*)Rh, (uint2*)Rl, n4);

    dim3 grid(L / QT, H, B);
    dim3 block(THREADS);
    // step 1: Q=R -> split tmp
    hopfield_mma<<<grid, block>>>(Rh, Rl, Yh, Yl, nullptr, Th, Tl, L, S);
    // step 2: Q=tmp -> fp32 out
    hopfield_mma<<<grid, block>>>(Th, Tl, Yh, Yl, out, nullptr, nullptr, L, S);
}